// round 5
// baseline (speedup 1.0000x reference)
#include <cuda_runtime.h>
#include <math.h>
#include <float.h>

#define T_    4
#define C_    64
#define WW    96
#define HW    9216
#define CI    16
#define PS    7
#define WS    21
#define NQX   24
#define NQ    576
#define NC    441
#define KSEL  100
#define SCALE 10.0f
#define RGN   27
#define RGN2  729
#define NT    256
#define NTS   384
#define B1P   56
#define QST   (RGN*WS)      // 567

// smem layout (float offsets)
#define SM_B1   0            // 896
#define SM_RG   896          // 11664
#define SM_Q    12560        // 3970
#define SM_QB   16530        // 3970
#define SM_SRT  20500        // u64[512] = 1024 floats
#define SM_W    21524        // 104
#define SM_CID  21628        // 100
#define SM_RO   21728        // 147
#define SM_CO   21875        // 147
#define SM_GOFF 22022        // 729
#define SM_TOT  22751        // 91004 bytes

typedef unsigned long long ull;

// scratch
__device__ float g_b1[T_*CI*HW];
__device__ float g_b2[T_*CI*HW];
__device__ float g_b3[T_*CI*HW];
__device__ float g_acc[T_*CI*HW];
__device__ float g_Z[HW];

__device__ __forceinline__ int clipi(int v){ return min(max(v,0),95); }
__device__ __forceinline__ unsigned ordf(float f){
    unsigned b = __float_as_uint(f);
    return (b & 0x80000000u) ? ~b : (b | 0x80000000u);
}
__device__ __forceinline__ float iordf(unsigned u){
    unsigned b = (u & 0x80000000u) ? (u & 0x7FFFFFFFu) : ~u;
    return __uint_as_float(b);
}
__device__ __forceinline__ ull pack2(float lo, float hi){
    ull r; asm("mov.b64 %0, {%1, %2};" : "=l"(r) : "f"(lo), "f"(hi)); return r;
}
__device__ __forceinline__ void fma2(ull &acc, ull a, ull b){
    asm("fma.rn.f32x2 %0, %1, %2, %0;" : "+l"(acc) : "l"(a), "l"(b));
}
__device__ __forceinline__ float sum2(ull v){
    return __uint_as_float((unsigned)v) + __uint_as_float((unsigned)(v>>32));
}

// ---------------------------------------------------------------- zero
__global__ void k_zero(){
    int i = blockIdx.x*NT + threadIdx.x;
    if (i < T_*CI*HW) g_acc[i] = 0.f;
    if (i < HW)       g_Z[i]   = 0.f;
}

// ---------------------------------------------------------------- Z counts
__global__ void k_zcount(){
    int q  = blockIdx.x;
    int a  = threadIdx.x / PS, b = threadIdx.x % PS;
    int qi = (q / NQX)*4, qj = (q % NQX)*4;
    atomicAdd(&g_Z[min(qi+a,95)*WW + min(qj+b,95)], 1.0f);
}

// ---------------------------------------------------------------- fused 3x conv1x1
__global__ void k_proj(const float* __restrict__ vid,
                       const float* __restrict__ gw, const float* __restrict__ gb,
                       const float* __restrict__ tw, const float* __restrict__ tb,
                       const float* __restrict__ pw, const float* __restrict__ pb){
    __shared__ float sw[3*CI*C_ + 3*CI];
    for (int i=threadIdx.x; i<CI*C_; i+=NT){
        sw[i]          = gw[i];
        sw[CI*C_+i]    = tw[i];
        sw[2*CI*C_+i]  = pw[i];
    }
    if (threadIdx.x < CI){
        sw[3*CI*C_         + threadIdx.x] = gb[threadIdx.x];
        sw[3*CI*C_ +   CI  + threadIdx.x] = tb[threadIdx.x];
        sw[3*CI*C_ + 2*CI  + threadIdx.x] = pb[threadIdx.x];
    }
    __syncthreads();

    int gid = blockIdx.x*NT + threadIdx.x;
    int t = gid / HW, pix = gid % HW;

    float a1[CI], a2[CI], a3[CI];
    #pragma unroll
    for (int o=0;o<CI;o++){
        a1[o] = sw[3*CI*C_ + o];
        a2[o] = sw[3*CI*C_ + CI + o];
        a3[o] = sw[3*CI*C_ + 2*CI + o];
    }
    const float* vp = vid + (size_t)t*C_*HW + pix;
    for (int c=0;c<C_;c++){
        float v = vp[c*HW];
        #pragma unroll
        for (int o=0;o<CI;o++){
            a1[o] += v*sw[o*C_+c];
            a2[o] += v*sw[CI*C_ + o*C_+c];
            a3[o] += v*sw[2*CI*C_ + o*C_+c];
        }
    }
    float* o1 = g_b1 + (size_t)t*CI*HW + pix;
    float* o2 = g_b2 + (size_t)t*CI*HW + pix;
    float* o3 = g_b3 + (size_t)t*CI*HW + pix;
    #pragma unroll
    for (int o=0;o<CI;o++){ o1[o*HW]=a1[o]; o2[o*HW]=a2[o]; o3[o*HW]=a3[o]; }
}

// ---------------------------------------------------------------- main kernel
__global__ void __launch_bounds__(NTS, 2) k_score(){
    extern __shared__ float sm[];
    float* s_b1 = sm + SM_B1;
    float* s_rg = sm + SM_RG;
    float4* s_rg4 = (float4*)(sm + SM_RG);   // b2 interleaved layout (aliases s_rg)
    float* s_Q  = sm + SM_Q;
    float* s_QB = sm + SM_QB;
    ull*   s_srt = (ull*)(sm + SM_SRT);
    float* s_w   = sm + SM_W;
    int*   s_cid = (int*)(sm + SM_CID);
    int*   s_ro  = (int*)(sm + SM_RO);
    int*   s_co  = (int*)(sm + SM_CO);
    int*   s_goff= (int*)(sm + SM_GOFF);
    int*   s_offT= (int*)s_Q;    // alias Q/QB (dead after softmax): 4900 <= 7940

    int blk = blockIdx.x;
    int t = blk / NQ, q = blk % NQ;
    int qi = (q / NQX)*4, qj = (q % NQX)*4;
    int tid = threadIdx.x;

    int rmin = max(qi-10, 0), cmin = max(qj-10, 0);
    bool colAffine = (qj >= 12 && qj <= 76);

    // ---- tables
    if (tid < 147){
        int d_ = tid/7, e_ = tid%7;
        s_ro[tid] = min(clipi(qi + d_ - 10) + e_, 95) - rmin;
        s_co[tid] = min(clipi(qj + d_ - 10) + e_, 95) - cmin;
    }
    for (int i=tid; i<RGN2; i+=NTS){
        int rr = i/RGN, cc = i - rr*RGN;
        s_goff[i] = min(rmin+rr,95)*WW + min(cmin+cc,95);
    }
    const float* b1t = g_b1 + (size_t)t*CI*HW;
    for (int i=tid; i<CI*49; i+=NTS){
        int ci = i/49, rem = i - 49*ci, a = rem/7, b = rem - 7*a;
        s_b1[ci*B1P + a*8 + b] = b1t[ci*HW + min(qi+a,95)*WW + min(qj+b,95)];
    }
    if (tid < CI*7){
        int ci = tid/7, a = tid - 7*ci;
        s_b1[ci*B1P + a*8 + 7] = 0.f;
    }
    __syncthreads();

    // ---- load b3 region (planar): 1 goff LDS feeds 16 independent LDGs
    {
        const float* b3t = g_b3 + (size_t)t*CI*HW;
        for (int i=tid; i<RGN2; i+=NTS){
            int go = s_goff[i];
            #pragma unroll
            for (int ci=0;ci<CI;ci++) s_rg[ci*RGN2+i] = b3t[ci*HW+go];
        }
    }
    __syncthreads();

    // ---- stage 1 (split over ci halves): Q[a][r][dj] via f32x2
    {
        int tid1 = (tid < 192) ? tid : tid - 192;
        int ci0  = (tid < 192) ? 0 : 8;
        float* Qp = (tid < 192) ? s_Q : s_QB;
        if (tid1 < 189){
            int r = tid1/7, dj0 = (tid1%7)*3;
            ull acc2[7][3];
            #pragma unroll
            for (int a=0;a<7;a++){ acc2[a][0]=0ull; acc2[a][1]=0ull; acc2[a][2]=0ull; }

            if (colAffine){
                for (int cc=0; cc<8; cc++){
                    int ci = ci0 + cc;
                    const float* row = s_rg + ci*RGN2 + r*RGN + dj0;
                    float win[9];
                    #pragma unroll
                    for (int j=0;j<9;j++) win[j] = row[j];
                    ull wp[9];
                    #pragma unroll
                    for (int b=0;b<8;b++) wp[b] = pack2(win[b], win[b+1]);
                    wp[8] = pack2(win[8], 0.f);
                    const ull* wq = (const ull*)(s_b1 + ci*B1P);
                    #pragma unroll
                    for (int a=0;a<7;a++){
                        ull w01 = wq[a*4+0], w23 = wq[a*4+1], w45 = wq[a*4+2], w67 = wq[a*4+3];
                        #pragma unroll
                        for (int k=0;k<3;k++){
                            fma2(acc2[a][k], w01, wp[k]);
                            fma2(acc2[a][k], w23, wp[k+2]);
                            fma2(acc2[a][k], w45, wp[k+4]);
                            fma2(acc2[a][k], w67, wp[k+6]);
                        }
                    }
                }
            } else {
                int clim = 95 - cmin;
                int cb[3];
                #pragma unroll
                for (int k=0;k<3;k++) cb[k] = s_co[(dj0+k)*7];
                for (int cc=0; cc<8; cc++){
                    int ci = ci0 + cc;
                    const float* row = s_rg + ci*RGN2 + r*RGN;
                    ull vp[3][4];
                    #pragma unroll
                    for (int k=0;k<3;k++){
                        float w0=row[min(cb[k]+0,clim)], w1=row[min(cb[k]+1,clim)];
                        float w2=row[min(cb[k]+2,clim)], w3=row[min(cb[k]+3,clim)];
                        float w4=row[min(cb[k]+4,clim)], w5=row[min(cb[k]+5,clim)];
                        float w6=row[min(cb[k]+6,clim)], w7=row[min(cb[k]+7,clim)];
                        vp[k][0]=pack2(w0,w1); vp[k][1]=pack2(w2,w3);
                        vp[k][2]=pack2(w4,w5); vp[k][3]=pack2(w6,w7);
                    }
                    const ull* wq = (const ull*)(s_b1 + ci*B1P);
                    #pragma unroll
                    for (int a=0;a<7;a++){
                        ull w01 = wq[a*4+0], w23 = wq[a*4+1], w45 = wq[a*4+2], w67 = wq[a*4+3];
                        #pragma unroll
                        for (int k=0;k<3;k++){
                            fma2(acc2[a][k], w01, vp[k][0]);
                            fma2(acc2[a][k], w23, vp[k][1]);
                            fma2(acc2[a][k], w45, vp[k][2]);
                            fma2(acc2[a][k], w67, vp[k][3]);
                        }
                    }
                }
            }
            #pragma unroll
            for (int a=0;a<7;a++)
                #pragma unroll
                for (int k=0;k<3;k++)
                    Qp[a*QST + r*WS + dj0 + k] = sum2(acc2[a][k]);
        }
    }
    __syncthreads();

    // ---- prefetch b2 region into registers (hidden behind stage2+sort)
    const float* b2t = g_b2 + (size_t)t*CI*HW;
    float vb[CI], vb2[CI];
    {
        int go0 = s_goff[tid];
        #pragma unroll
        for (int ci=0;ci<CI;ci++) vb[ci] = b2t[ci*HW+go0];
        if (tid + NTS < RGN2){
            int go1 = s_goff[tid+NTS];
            #pragma unroll
            for (int ci=0;ci<CI;ci++) vb2[ci] = b2t[ci*HW+go1];
        }
    }

    // ---- stage 2: scores (sum both ci-halves) -> packed sort keys
    for (int c=tid; c<512; c+=NTS){
        ull key = 0ull;
        if (c < NC){
            int di = c/WS, dj = c - WS*di;
            float sc = 0.f;
            #pragma unroll
            for (int a=0;a<7;a++){
                int qo = a*QST + s_ro[di*7+a]*WS + dj;
                sc += s_Q[qo] + s_QB[qo];
            }
            key = ((ull)ordf(sc) << 32) | (unsigned)c;
        }
        s_srt[c] = key;
    }

    // ---- bitonic sort 512 u64 descending (first 256 threads work; all sync)
    for (int k=2; k<=512; k<<=1){
        for (int j=k>>1; j>0; j>>=1){
            __syncthreads();
            if (tid < 256){
                int lo = tid & (j-1);
                int i0 = ((tid & ~(j-1))<<1) | lo;
                int i1 = i0 | j;
                bool desc = (i0 & k) == 0;
                ull k0 = s_srt[i0], k1 = s_srt[i1];
                if ((k0 < k1) == desc){ s_srt[i0]=k1; s_srt[i1]=k0; }
            }
        }
    }
    __syncthreads();

    // ---- softmax over top-100
    {
        float maxs = iordf((unsigned)(s_srt[0] >> 32));
        if (tid < KSEL){
            ull key = s_srt[tid];
            float sc = iordf((unsigned)(key >> 32));
            s_w[tid]   = expf((sc - maxs)*SCALE);
            s_cid[tid] = (int)(key & 0x1FFu);
        }
        __syncthreads();
        if (tid < 32){
            float s = 0.f;
            for (int k=tid; k<KSEL; k+=32) s += s_w[k];
            #pragma unroll
            for (int o=16;o;o>>=1) s += __shfl_xor_sync(0xffffffffu, s, o);
            if (tid == 0) s_w[KSEL] = 1.f/s;
        }
        __syncthreads();
        if (tid < KSEL) s_w[tid] *= s_w[KSEL];
    }

    // ---- commit prefetched b2 in ci-interleaved float4 layout + offset table
    #pragma unroll
    for (int g=0; g<4; g++)
        s_rg4[g*RGN2 + tid] = make_float4(vb[g*4+0], vb[g*4+1], vb[g*4+2], vb[g*4+3]);
    if (tid + NTS < RGN2){
        #pragma unroll
        for (int g=0; g<4; g++)
            s_rg4[g*RGN2 + tid + NTS] = make_float4(vb2[g*4+0], vb2[g*4+1], vb2[g*4+2], vb2[g*4+3]);
    }
    for (int i=tid; i<KSEL*49; i+=NTS){
        int k = i/49, p = i - 49*k;
        int c = s_cid[k];
        int pa = p/7, pb = p - 7*pa;
        s_offT[p*100 + k] = s_ro[(c/WS)*7 + pa]*RGN + s_co[(c%WS)*7 + pb];
    }
    __syncthreads();

    // ---- aggregation: 196 threads, 1 LDS.128 gather per (k, cig)
    if (tid < 196){
        int p   = tid % 49;
        int cig = tid / 49;
        const float4* rg = s_rg4 + cig*RGN2;
        const int*   offp = s_offT + p*100;
        float a0=0.f, a1=0.f, a2=0.f, a3=0.f;
        #pragma unroll
        for (int k=0; k<KSEL; k+=4){
            int4   o4 = *(const int4*)  (offp + k);
            float4 w4 = *(const float4*)(s_w + k);
            float4 v0 = rg[o4.x], v1 = rg[o4.y], v2 = rg[o4.z], v3 = rg[o4.w];
            a0 += w4.x*v0.x; a1 += w4.x*v0.y; a2 += w4.x*v0.z; a3 += w4.x*v0.w;
            a0 += w4.y*v1.x; a1 += w4.y*v1.y; a2 += w4.y*v1.z; a3 += w4.y*v1.w;
            a0 += w4.z*v2.x; a1 += w4.z*v2.y; a2 += w4.z*v2.z; a3 += w4.z*v2.w;
            a0 += w4.w*v3.x; a1 += w4.w*v3.y; a2 += w4.w*v3.z; a3 += w4.w*v3.w;
        }
        int pa = p/7, pb = p - 7*pa;
        int pix = min(qi+pa,95)*WW + min(qj+pb,95);
        float* accb = g_acc + (size_t)(t*CI + cig*4)*HW + pix;
        atomicAdd(accb,        a0);
        atomicAdd(accb +   HW, a1);
        atomicAdd(accb + 2*HW, a2);
        atomicAdd(accb + 3*HW, a3);
    }
}

// ---------------------------------------------------------------- y = acc/Z ; out = vid + conv1x1(y)
__global__ void k_final(const float* __restrict__ vid, const float* __restrict__ Ww,
                        const float* __restrict__ Wb, float* __restrict__ out){
    __shared__ float sw[C_*CI + C_];
    for (int i=threadIdx.x; i<C_*CI; i+=NT) sw[i] = Ww[i];
    if (threadIdx.x < C_) sw[C_*CI+threadIdx.x] = Wb[threadIdx.x];
    __syncthreads();

    int gid = blockIdx.x*NT + threadIdx.x;
    int t = gid / HW, pix = gid % HW;

    float inv = 1.f / g_Z[pix];
    float y[CI];
    #pragma unroll
    for (int ci=0;ci<CI;ci++) y[ci] = g_acc[(t*CI+ci)*HW + pix]*inv;

    const float* vp = vid + (size_t)t*C_*HW + pix;
    float*       op = out + (size_t)t*C_*HW + pix;
    for (int co=0;co<C_;co++){
        float s = sw[C_*CI+co];
        #pragma unroll
        for (int ci=0;ci<CI;ci++) s += sw[co*CI+ci]*y[ci];
        op[co*HW] = vp[co*HW] + s;
    }
}

// ---------------------------------------------------------------- launch
extern "C" void kernel_launch(void* const* d_in, const int* in_sizes, int n_in,
                              void* d_out, int out_size){
    const float* vid  = (const float*)d_in[0];
    const float* g_w  = (const float*)d_in[1];
    const float* g_b  = (const float*)d_in[2];
    const float* th_w = (const float*)d_in[3];
    const float* th_b = (const float*)d_in[4];
    const float* ph_w = (const float*)d_in[5];
    const float* ph_b = (const float*)d_in[6];
    const float* W_w  = (const float*)d_in[7];
    const float* W_b  = (const float*)d_in[8];
    float* out = (float*)d_out;

    const int SMEM = SM_TOT * 4;   // 91004 B
    cudaFuncSetAttribute(k_score, cudaFuncAttributeMaxDynamicSharedMemorySize, SMEM);

    k_zero  <<<(T_*CI*HW + NT-1)/NT, NT>>>();
    k_proj  <<<T_*HW/NT, NT>>>(vid, g_w, g_b, th_w, th_b, ph_w, ph_b);
    k_zcount<<<NQ, PS*PS>>>();
    k_score <<<T_*NQ, NTS, SMEM>>>();
    k_final <<<T_*HW/NT, NT>>>(vid, W_w, W_b, out);
}